// round 1
// baseline (speedup 1.0000x reference)
#include <cuda_runtime.h>
#include <cuda_bf16.h>
#include <math.h>

// ---------------------------------------------------------------------------
// BoundaryAwareViT fp32 baseline.
// B=32, IMG=512, P=16, D=256, DEPTH=8, G=32, N=1024, DQ=32, DF=1024, M=B*N=32768
// ---------------------------------------------------------------------------

#define Mtok  32768       // B*N
#define Dd    256
#define DQq   32
#define DFf   1024
#define Gg    32
#define Nn    1024

// Scratch (static device globals; allocation APIs are forbidden)
__device__ float g_im [Mtok * Dd];    // im2col patches [M,256]
__device__ float g_h  [Mtok * Dd];    // token stream
__device__ float g_xn [Mtok * Dd];    // LN output
__device__ float g_lap[Mtok * Dd];    // laplacian
__device__ float g_q  [Mtok * DQq];
__device__ float g_k  [Mtok * DQq];
__device__ float g_v  [Mtok * Dd];
__device__ float g_mid[Mtok * DFf];   // FFN hidden
__device__ float g_wpT[Dd * Dd];      // w_patch transposed to [K=256, N=256]

// ---------------------------------------------------------------------------
// small helpers
// ---------------------------------------------------------------------------
__global__ void transpose_wp_k(const float* __restrict__ wp, float* __restrict__ out) {
    int idx = blockIdx.x * 256 + threadIdx.x;       // 65536
    int d = idx >> 8, k = idx & 255;
    out[k * Dd + d] = wp[d * 256 + k];
}

// im2col: A[(b*1024+gh*32+gw)*256 + pr*16+pc] = x[(b*512 + gh*16+pr)*512 + gw*16+pc]
__global__ void im2col_k(const float* __restrict__ x, float* __restrict__ out) {
    int idx = blockIdx.x * 256 + threadIdx.x;       // 32768*256
    int pc  = idx & 15;
    int pr  = (idx >> 4) & 15;
    int tok = idx >> 8;
    int gw  = tok & 31, gh = (tok >> 5) & 31, b = tok >> 10;
    out[idx] = x[((b * 512) + gh * 16 + pr) * 512 + gw * 16 + pc];
}

// Laplacian over token grid with zero ('SAME') padding
__global__ void lap_k(const float* __restrict__ t, float* __restrict__ out) {
    int tok = blockIdx.x;
    int d   = threadIdx.x;
    int gw = tok & 31, gh = (tok >> 5) & 31;
    float c = 4.0f * t[tok * Dd + d];
    if (gh > 0)  c -= t[(tok - 32) * Dd + d];
    if (gh < 31) c -= t[(tok + 32) * Dd + d];
    if (gw > 0)  c -= t[(tok - 1) * Dd + d];
    if (gw < 31) c -= t[(tok + 1) * Dd + d];
    out[tok * Dd + d] = c;
}

// LayerNorm over D=256, one block per token, 256 threads
__global__ void ln_k(const float* __restrict__ h, float* __restrict__ xn,
                     const float* __restrict__ g, const float* __restrict__ b) {
    int m = blockIdx.x;
    int d = threadIdx.x;
    float val = h[m * Dd + d];
    float s = val, sq = val * val;
    #pragma unroll
    for (int o = 16; o > 0; o >>= 1) {
        s  += __shfl_xor_sync(0xFFFFFFFFu, s,  o);
        sq += __shfl_xor_sync(0xFFFFFFFFu, sq, o);
    }
    __shared__ float s1[8], s2[8];
    int lane = d & 31, w = d >> 5;
    if (lane == 0) { s1[w] = s; s2[w] = sq; }
    __syncthreads();
    __shared__ float mean_s, rstd_s;
    if (d == 0) {
        float S = 0, SQ = 0;
        #pragma unroll
        for (int i = 0; i < 8; i++) { S += s1[i]; SQ += s2[i]; }
        float mean = S * (1.0f / 256.0f);
        float var  = SQ * (1.0f / 256.0f) - mean * mean;
        mean_s = mean;
        rstd_s = rsqrtf(var + 1e-5f);
    }
    __syncthreads();
    xn[m * Dd + d] = (val - mean_s) * rstd_s * g[d] + b[d];
}

// ---------------------------------------------------------------------------
// Tiled SGEMM 128x128x8, 256 threads, 8x8 per thread.
// C[M,N] = A[M,K] @ B[K,N] + bias[n], epilogue by MODE.
//   MODE 0: store        C = acc+bias
//   MODE 1: store+pos    C = acc+bias + extra[(m%1024)*N + n]
//   MODE 2: add tanh     C += tanhf(acc+bias)
//   MODE 3: gelu         C = gelu(acc+bias)  (exact erf)
//   MODE 4: add          C += acc+bias
// M % 128 == 0 and K % 8 == 0 always hold here; N may be 32 (guarded).
// ---------------------------------------------------------------------------
template<int MODE>
__global__ void __launch_bounds__(256, 2)
gemm128(const float* __restrict__ A, const float* __restrict__ B,
        const float* __restrict__ bias, float* __restrict__ C,
        const float* __restrict__ extra, int M, int N, int K)
{
    __shared__ float As[8][128];
    __shared__ float Bs[8][128];
    int tid = threadIdx.x;
    int bx = blockIdx.x, by = blockIdx.y;
    int tx = tid & 15, ty = tid >> 4;
    int row0 = by * 128, col0 = bx * 128;

    int aRow = tid >> 1;
    int aCol = (tid & 1) * 4;
    int bRow = tid >> 5;
    int bCol = (tid & 31) * 4;

    float acc[8][8];
    #pragma unroll
    for (int i = 0; i < 8; i++)
        #pragma unroll
        for (int j = 0; j < 8; j++) acc[i][j] = 0.0f;

    const float* Aptr = A + (size_t)(row0 + aRow) * K + aCol;

    for (int k0 = 0; k0 < K; k0 += 8) {
        float4 a4 = *(const float4*)(Aptr + k0);
        As[aCol + 0][aRow] = a4.x;
        As[aCol + 1][aRow] = a4.y;
        As[aCol + 2][aRow] = a4.z;
        As[aCol + 3][aRow] = a4.w;
        float4 b4 = make_float4(0.f, 0.f, 0.f, 0.f);
        if (col0 + bCol < N)
            b4 = *(const float4*)(B + (size_t)(k0 + bRow) * N + col0 + bCol);
        *(float4*)&Bs[bRow][bCol] = b4;
        __syncthreads();
        #pragma unroll
        for (int kk = 0; kk < 8; kk++) {
            float ra[8], rb[8];
            #pragma unroll
            for (int i = 0; i < 8; i++) ra[i] = As[kk][ty * 8 + i];
            #pragma unroll
            for (int j = 0; j < 8; j++) rb[j] = Bs[kk][tx * 8 + j];
            #pragma unroll
            for (int i = 0; i < 8; i++)
                #pragma unroll
                for (int j = 0; j < 8; j++)
                    acc[i][j] = fmaf(ra[i], rb[j], acc[i][j]);
        }
        __syncthreads();
    }

    #pragma unroll
    for (int i = 0; i < 8; i++) {
        int m = row0 + ty * 8 + i;
        #pragma unroll
        for (int j = 0; j < 8; j++) {
            int n = col0 + tx * 8 + j;
            if (n < N) {
                float val = acc[i][j] + bias[n];
                size_t idx = (size_t)m * N + n;
                if (MODE == 0) {
                    C[idx] = val;
                } else if (MODE == 1) {
                    C[idx] = val + extra[(size_t)(m & 1023) * N + n];
                } else if (MODE == 2) {
                    C[idx] += tanhf(val);
                } else if (MODE == 3) {
                    C[idx] = val * 0.5f * (1.0f + erff(val * 0.70710678118654752f));
                } else { // 4
                    C[idx] += val;
                }
            }
        }
    }
}

// ---------------------------------------------------------------------------
// Criss-cross attention, one block per token, 256 threads.
// h[m,d] = h[m,d] + xn[m,d] + gamma * out[m,d]
// ---------------------------------------------------------------------------
__global__ void attn_k(const float* __restrict__ q, const float* __restrict__ k,
                       const float* __restrict__ v, const float* __restrict__ xn,
                       float* __restrict__ h, const float* __restrict__ gamma_all,
                       int layer)
{
    int tok = blockIdx.x;               // b*1024 + gh*32 + gw
    int gw = tok & 31, gh = (tok >> 5) & 31, b = tok >> 10;
    int tid = threadIdx.x;

    __shared__ float qs[32];
    __shared__ float krow[32 * 32];
    __shared__ float kcol[32 * 32];
    __shared__ float a[64];

    if (tid < 32) qs[tid] = q[tok * DQq + tid];

    // krow: k[b, gh, j, c] — contiguous 1024 floats
    {
        const float* kr = k + (size_t)(b * Nn + gh * 32) * DQq;
        for (int i = tid; i < 1024; i += 256) krow[i] = kr[i];
        // kcol: k[b, j, gw, c]
        int j = tid >> 5, c = tid & 31;
        for (int jj = j; jj < 32; jj += 8)
            kcol[jj * 32 + c] = k[(size_t)(b * Nn + jj * 32 + gw) * DQq + c];
    }
    __syncthreads();

    if (tid < 64) {
        int j = tid & 31;
        const float* kk = (tid < 32) ? &krow[j * 32] : &kcol[j * 32];
        float s = 0.0f;
        #pragma unroll
        for (int c = 0; c < 32; c++) s = fmaf(qs[c], kk[c], s);
        s *= 0.17677669529663687f;      // 1/sqrt(32)
        if (tid >= 32 && j == gh) s -= 1e9f;
        a[tid] = s;
    }
    __syncthreads();

    if (tid < 32) {
        float m2 = fmaxf(a[tid], a[tid + 32]);
        #pragma unroll
        for (int o = 16; o > 0; o >>= 1) m2 = fmaxf(m2, __shfl_xor_sync(0xFFFFFFFFu, m2, o));
        float e0 = expf(a[tid] - m2), e1 = expf(a[tid + 32] - m2);
        float s = e0 + e1;
        #pragma unroll
        for (int o = 16; o > 0; o >>= 1) s += __shfl_xor_sync(0xFFFFFFFFu, s, o);
        float inv = 1.0f / s;
        a[tid] = e0 * inv;
        a[tid + 32] = e1 * inv;
    }
    __syncthreads();

    float accv = 0.0f;
    const float* vrow = v + (size_t)(b * Nn + gh * 32) * Dd;   // v[b,gh,j,d]
    #pragma unroll 8
    for (int j = 0; j < 32; j++) accv = fmaf(a[j], vrow[j * Dd + tid], accv);
    #pragma unroll 8
    for (int j = 0; j < 32; j++)
        accv = fmaf(a[32 + j], v[(size_t)(b * Nn + j * 32 + gw) * Dd + tid], accv);

    float gm = gamma_all[layer];
    size_t idx = (size_t)tok * Dd + tid;
    h[idx] = h[idx] + xn[idx] + gm * accv;
}

// ---------------------------------------------------------------------------
// Head: out[b*N + tok_in_batch] = dot(h[m,:], w_head) + b_head
// (output layout [B,1,G,G] == flat [B*N])
// ---------------------------------------------------------------------------
__global__ void head_k(const float* __restrict__ h, const float* __restrict__ w,
                       const float* __restrict__ bh, float* __restrict__ out)
{
    int m = blockIdx.x;
    int d = threadIdx.x;
    float p = h[(size_t)m * Dd + d] * w[d];
    #pragma unroll
    for (int o = 16; o > 0; o >>= 1) p += __shfl_xor_sync(0xFFFFFFFFu, p, o);
    __shared__ float s1[8];
    int lane = d & 31, wr = d >> 5;
    if (lane == 0) s1[wr] = p;
    __syncthreads();
    if (d == 0) {
        float S = 0;
        #pragma unroll
        for (int i = 0; i < 8; i++) S += s1[i];
        out[m] = S + bh[0];
    }
}

// ---------------------------------------------------------------------------
extern "C" void kernel_launch(void* const* d_in, const int* in_sizes, int n_in,
                              void* d_out, int out_size)
{
    const float* x       = (const float*)d_in[0];
    const float* w_patch = (const float*)d_in[1];
    const float* b_patch = (const float*)d_in[2];
    const float* pos     = (const float*)d_in[3];
    const float* w_edge  = (const float*)d_in[4];
    const float* b_edge  = (const float*)d_in[5];
    const float* ln_g    = (const float*)d_in[6];
    const float* ln_b    = (const float*)d_in[7];
    const float* wq      = (const float*)d_in[8];
    const float* bq      = (const float*)d_in[9];
    const float* wk      = (const float*)d_in[10];
    const float* bk      = (const float*)d_in[11];
    const float* wv      = (const float*)d_in[12];
    const float* bv      = (const float*)d_in[13];
    const float* gamma   = (const float*)d_in[14];
    const float* w1      = (const float*)d_in[15];
    const float* b1      = (const float*)d_in[16];
    const float* w2      = (const float*)d_in[17];
    const float* b2      = (const float*)d_in[18];
    const float* w_head  = (const float*)d_in[19];
    const float* b_head  = (const float*)d_in[20];
    float* out = (float*)d_out;

    float *im, *h, *xn, *lap, *q, *k, *v, *mid, *wpT;
    cudaGetSymbolAddress((void**)&im,  g_im);
    cudaGetSymbolAddress((void**)&h,   g_h);
    cudaGetSymbolAddress((void**)&xn,  g_xn);
    cudaGetSymbolAddress((void**)&lap, g_lap);
    cudaGetSymbolAddress((void**)&q,   g_q);
    cudaGetSymbolAddress((void**)&k,   g_k);
    cudaGetSymbolAddress((void**)&v,   g_v);
    cudaGetSymbolAddress((void**)&mid, g_mid);
    cudaGetSymbolAddress((void**)&wpT, g_wpT);

    const int M = Mtok;
    dim3 b256(256);

    // patch embed
    transpose_wp_k<<<256, b256>>>(w_patch, wpT);
    im2col_k<<<Mtok, b256>>>(x, im);
    gemm128<1><<<dim3(2, M / 128), b256>>>(im, wpT, b_patch, h, pos, M, Dd, Dd);

    // edge tokens: h += tanh(lap(h) @ w_edge + b_edge)
    lap_k<<<Mtok, b256>>>(h, lap);
    gemm128<2><<<dim3(2, M / 128), b256>>>(lap, w_edge, b_edge, h, nullptr, M, Dd, Dd);

    // transformer blocks
    for (int l = 0; l < 8; l++) {
        ln_k<<<Mtok, b256>>>(h, xn, ln_g + l * Dd, ln_b + l * Dd);
        gemm128<0><<<dim3(1, M / 128), b256>>>(xn, wq + l * Dd * DQq, bq + l * DQq, q, nullptr, M, DQq, Dd);
        gemm128<0><<<dim3(1, M / 128), b256>>>(xn, wk + l * Dd * DQq, bk + l * DQq, k, nullptr, M, DQq, Dd);
        gemm128<0><<<dim3(2, M / 128), b256>>>(xn, wv + l * Dd * Dd,  bv + l * Dd,  v, nullptr, M, Dd, Dd);
        attn_k<<<Mtok, b256>>>(q, k, v, xn, h, gamma, l);

        ln_k<<<Mtok, b256>>>(h, xn, ln_g + l * Dd, ln_b + l * Dd);
        gemm128<3><<<dim3(8, M / 128), b256>>>(xn, w1 + l * Dd * DFf, b1 + l * DFf, mid, nullptr, M, DFf, Dd);
        gemm128<4><<<dim3(2, M / 128), b256>>>(mid, w2 + l * DFf * Dd, b2 + l * Dd, h, nullptr, M, Dd, DFf);
    }

    head_k<<<Mtok, b256>>>(h, w_head, b_head, out);
}

// round 2
// speedup vs baseline: 2.0801x; 2.0801x over previous
#include <cuda_runtime.h>
#include <cuda_bf16.h>
#include <math.h>
#include <stdint.h>

// ---------------------------------------------------------------------------
// BoundaryAwareViT — tf32 tensor-core GEMMs + blocked criss-cross attention.
// B=32, IMG=512, P=16, D=256, DEPTH=8, G=32, N=1024, DQ=32, DF=1024, M=32768
// ---------------------------------------------------------------------------

#define Mtok  32768
#define Dd    256
#define DQq   32
#define DFf   1024
#define Nn    1024

__device__ float g_im [Mtok * Dd];
__device__ float g_h  [Mtok * Dd];
__device__ float g_xn [Mtok * Dd];
__device__ float g_lap[Mtok * Dd];
__device__ float g_q  [Mtok * DQq];
__device__ float g_k  [Mtok * DQq];
__device__ float g_v  [Mtok * Dd];
__device__ float g_mid[Mtok * DFf];
__device__ float g_att[Mtok * 64];
__device__ float g_wpT[Dd * Dd];

__device__ __forceinline__ uint32_t f2tf(float f) {
    uint32_t u;
    asm("cvt.rna.tf32.f32 %0, %1;" : "=r"(u) : "f"(f));
    return u;
}

// ---------------------------------------------------------------------------
// small helpers
// ---------------------------------------------------------------------------
__global__ void transpose_wp_k(const float* __restrict__ wp, float* __restrict__ out) {
    int idx = blockIdx.x * 256 + threadIdx.x;
    int d = idx >> 8, k = idx & 255;
    out[k * Dd + d] = wp[d * 256 + k];
}

__global__ void im2col_k(const float* __restrict__ x, float* __restrict__ out) {
    int idx = blockIdx.x * 256 + threadIdx.x;
    int pc  = idx & 15;
    int pr  = (idx >> 4) & 15;
    int tok = idx >> 8;
    int gw  = tok & 31, gh = (tok >> 5) & 31, b = tok >> 10;
    out[idx] = x[((b * 512) + gh * 16 + pr) * 512 + gw * 16 + pc];
}

__global__ void lap_k(const float* __restrict__ t, float* __restrict__ out) {
    int tok = blockIdx.x;
    int d   = threadIdx.x;
    int gw = tok & 31, gh = (tok >> 5) & 31;
    float c = 4.0f * t[tok * Dd + d];
    if (gh > 0)  c -= t[(tok - 32) * Dd + d];
    if (gh < 31) c -= t[(tok + 32) * Dd + d];
    if (gw > 0)  c -= t[(tok - 1) * Dd + d];
    if (gw < 31) c -= t[(tok + 1) * Dd + d];
    out[tok * Dd + d] = c;
}

__global__ void ln_k(const float* __restrict__ h, float* __restrict__ xn,
                     const float* __restrict__ g, const float* __restrict__ b) {
    int m = blockIdx.x;
    int d = threadIdx.x;
    float val = h[m * Dd + d];
    float s = val, sq = val * val;
    #pragma unroll
    for (int o = 16; o > 0; o >>= 1) {
        s  += __shfl_xor_sync(0xFFFFFFFFu, s,  o);
        sq += __shfl_xor_sync(0xFFFFFFFFu, sq, o);
    }
    __shared__ float s1[8], s2[8];
    int lane = d & 31, w = d >> 5;
    if (lane == 0) { s1[w] = s; s2[w] = sq; }
    __syncthreads();
    __shared__ float mean_s, rstd_s;
    if (d == 0) {
        float S = 0, SQ = 0;
        #pragma unroll
        for (int i = 0; i < 8; i++) { S += s1[i]; SQ += s2[i]; }
        float mean = S * (1.0f / 256.0f);
        float var  = SQ * (1.0f / 256.0f) - mean * mean;
        mean_s = mean;
        rstd_s = rsqrtf(var + 1e-5f);
    }
    __syncthreads();
    xn[m * Dd + d] = (val - mean_s) * rstd_s * g[d] + b[d];
}

// ---------------------------------------------------------------------------
// tf32 tensor-core GEMM: C[M,N] = A[M,K] @ B[K,N] + bias, epilogue per MODE.
// 128x128 block, BK=32, 8 warps (2x4), warp tile 64x32, m16n8k8 tf32 mma.
//   MODE 0: C = val;  1: C = val + pos;  2: C += tanh(val);
//   MODE 3: C = gelu(val);  4: C += val
// M%128==0, K%32==0 guaranteed; N guarded (N may be 32).
// ---------------------------------------------------------------------------
template<int MODE>
__global__ void __launch_bounds__(256)
gemm_tc(const float* __restrict__ A, const float* __restrict__ Bm,
        const float* __restrict__ bias, float* __restrict__ C,
        const float* __restrict__ extra, int M, int N, int K)
{
    __shared__ uint32_t As[128][36];   // [m][k], bank-conflict-free for frags
    __shared__ uint32_t Bs[32][136];   // [k][n]
    const int tid  = threadIdx.x;
    const int warp = tid >> 5, lane = tid & 31;
    const int wm = warp >> 2, wn = warp & 3;
    const int row0 = blockIdx.y * 128, col0 = blockIdx.x * 128;
    const int g = lane >> 2, tg = lane & 3;

    float acc[4][4][4];
    #pragma unroll
    for (int i = 0; i < 4; i++)
        #pragma unroll
        for (int j = 0; j < 4; j++)
            #pragma unroll
            for (int e = 0; e < 4; e++) acc[i][j][e] = 0.0f;

    for (int k0 = 0; k0 < K; k0 += 32) {
        #pragma unroll
        for (int i = 0; i < 4; i++) {
            int idx = tid + i * 256;
            int r = idx >> 3, c = (idx & 7) * 4;
            float4 a4 = *(const float4*)(A + (size_t)(row0 + r) * K + (k0 + c));
            As[r][c + 0] = f2tf(a4.x);
            As[r][c + 1] = f2tf(a4.y);
            As[r][c + 2] = f2tf(a4.z);
            As[r][c + 3] = f2tf(a4.w);
        }
        #pragma unroll
        for (int i = 0; i < 4; i++) {
            int idx = tid + i * 256;
            int r = idx >> 5, c = (idx & 31) * 4;
            float4 b4 = make_float4(0.f, 0.f, 0.f, 0.f);
            if (col0 + c < N)
                b4 = *(const float4*)(Bm + (size_t)(k0 + r) * N + (col0 + c));
            Bs[r][c + 0] = f2tf(b4.x);
            Bs[r][c + 1] = f2tf(b4.y);
            Bs[r][c + 2] = f2tf(b4.z);
            Bs[r][c + 3] = f2tf(b4.w);
        }
        __syncthreads();

        #pragma unroll
        for (int kk = 0; kk < 4; kk++) {
            const int kb = kk * 8;
            uint32_t af[4][4], bf[4][2];
            #pragma unroll
            for (int mi = 0; mi < 4; mi++) {
                int m0 = wm * 64 + mi * 16;
                af[mi][0] = As[m0 + g    ][kb + tg    ];
                af[mi][1] = As[m0 + 8 + g][kb + tg    ];
                af[mi][2] = As[m0 + g    ][kb + 4 + tg];
                af[mi][3] = As[m0 + 8 + g][kb + 4 + tg];
            }
            #pragma unroll
            for (int nj = 0; nj < 4; nj++) {
                int n0 = wn * 32 + nj * 8;
                bf[nj][0] = Bs[kb + tg    ][n0 + g];
                bf[nj][1] = Bs[kb + 4 + tg][n0 + g];
            }
            #pragma unroll
            for (int mi = 0; mi < 4; mi++)
                #pragma unroll
                for (int nj = 0; nj < 4; nj++)
                    asm volatile(
                        "mma.sync.aligned.m16n8k8.row.col.f32.tf32.tf32.f32 "
                        "{%0,%1,%2,%3}, {%4,%5,%6,%7}, {%8,%9}, {%0,%1,%2,%3};"
                        : "+f"(acc[mi][nj][0]), "+f"(acc[mi][nj][1]),
                          "+f"(acc[mi][nj][2]), "+f"(acc[mi][nj][3])
                        : "r"(af[mi][0]), "r"(af[mi][1]),
                          "r"(af[mi][2]), "r"(af[mi][3]),
                          "r"(bf[nj][0]), "r"(bf[nj][1]));
        }
        __syncthreads();
    }

    #pragma unroll
    for (int mi = 0; mi < 4; mi++) {
        #pragma unroll
        for (int nj = 0; nj < 4; nj++) {
            int r0 = row0 + wm * 64 + mi * 16 + g;
            int c0 = col0 + wn * 32 + nj * 8 + tg * 2;
            #pragma unroll
            for (int e = 0; e < 4; e++) {
                int r = r0 + (e >> 1) * 8;
                int c = c0 + (e & 1);
                if (c < N) {
                    float val = acc[mi][nj][e] + bias[c];
                    size_t idx = (size_t)r * N + c;
                    if (MODE == 0) {
                        C[idx] = val;
                    } else if (MODE == 1) {
                        C[idx] = val + extra[(size_t)(r & 1023) * N + c];
                    } else if (MODE == 2) {
                        C[idx] += tanhf(val);
                    } else if (MODE == 3) {
                        C[idx] = val * 0.5f * (1.0f + erff(val * 0.70710678118654752f));
                    } else {
                        C[idx] += val;
                    }
                }
            }
        }
    }
}

// ---------------------------------------------------------------------------
// Attention scores + softmax: one warp per token -> att[tok][64]
// ---------------------------------------------------------------------------
__global__ void attn_score_k(const float* __restrict__ q, const float* __restrict__ k,
                             float* __restrict__ att)
{
    int warp = threadIdx.x >> 5;
    int lane = threadIdx.x & 31;
    int tok = blockIdx.x * 8 + warp;
    int gw = tok & 31, gh = (tok >> 5) & 31, b = tok >> 10;

    __shared__ float qs[8][32];
    qs[warp][lane] = q[(size_t)tok * DQq + lane];
    __syncwarp();

    const float* krow = k + (size_t)(b * Nn + gh * 32 + lane) * DQq;
    const float* kcol = k + (size_t)(b * Nn + lane * 32 + gw) * DQq;
    float sr = 0.f, sc = 0.f;
    #pragma unroll
    for (int c = 0; c < 32; c += 4) {
        float4 kr = *(const float4*)(krow + c);
        float4 kc = *(const float4*)(kcol + c);
        float q0 = qs[warp][c], q1 = qs[warp][c + 1], q2 = qs[warp][c + 2], q3 = qs[warp][c + 3];
        sr = fmaf(q0, kr.x, fmaf(q1, kr.y, fmaf(q2, kr.z, fmaf(q3, kr.w, sr))));
        sc = fmaf(q0, kc.x, fmaf(q1, kc.y, fmaf(q2, kc.z, fmaf(q3, kc.w, sc))));
    }
    const float scale = 0.17677669529663687f;   // 1/sqrt(32)
    sr *= scale;
    sc *= scale;
    if (lane == gh) sc -= 1e9f;

    float m2 = fmaxf(sr, sc);
    #pragma unroll
    for (int o = 16; o > 0; o >>= 1) m2 = fmaxf(m2, __shfl_xor_sync(0xFFFFFFFFu, m2, o));
    float e0 = expf(sr - m2), e1 = expf(sc - m2);
    float s = e0 + e1;
    #pragma unroll
    for (int o = 16; o > 0; o >>= 1) s += __shfl_xor_sync(0xFFFFFFFFu, s, o);
    float inv = 1.0f / s;
    att[(size_t)tok * 64 + lane]      = e0 * inv;
    att[(size_t)tok * 64 + 32 + lane] = e1 * inv;
}

// ---------------------------------------------------------------------------
// Apply row attention: block = (b, gh); 32 tokens share the V row.
// h += xn + gamma * out_row
// ---------------------------------------------------------------------------
__global__ void attn_apply_row_k(const float* __restrict__ att, const float* __restrict__ v,
                                 const float* __restrict__ xn, float* __restrict__ h,
                                 const float* __restrict__ gamma_all, int layer)
{
    int blk = blockIdx.x;            // b*32 + gh
    int b = blk >> 5, gh = blk & 31;
    int d = threadIdx.x;
    int base_tok = b * Nn + gh * 32;

    __shared__ float as_[32][32];
    for (int i = d; i < 1024; i += 256) {
        int t = i >> 5, j = i & 31;
        as_[t][j] = att[(size_t)(base_tok + t) * 64 + j];
    }
    __syncthreads();

    float acc[32];
    #pragma unroll
    for (int t = 0; t < 32; t++) acc[t] = 0.f;

    const float* vp = v + (size_t)base_tok * Dd + d;
    #pragma unroll 4
    for (int j = 0; j < 32; j++) {
        float vj = vp[j * Dd];
        #pragma unroll
        for (int t = 0; t < 32; t++) acc[t] = fmaf(as_[t][j], vj, acc[t]);
    }
    float gm = gamma_all[layer];
    #pragma unroll
    for (int t = 0; t < 32; t++) {
        size_t idx = (size_t)(base_tok + t) * Dd + d;
        h[idx] += xn[idx] + gm * acc[t];
    }
}

// ---------------------------------------------------------------------------
// Apply column attention: block = (b, gw); 32 tokens share the V column.
// h += gamma * out_col
// ---------------------------------------------------------------------------
__global__ void attn_apply_col_k(const float* __restrict__ att, const float* __restrict__ v,
                                 float* __restrict__ h,
                                 const float* __restrict__ gamma_all, int layer)
{
    int blk = blockIdx.x;            // b*32 + gw
    int b = blk >> 5, gw = blk & 31;
    int d = threadIdx.x;

    __shared__ float as_[32][32];
    for (int i = d; i < 1024; i += 256) {
        int t = i >> 5, j = i & 31;
        as_[t][j] = att[(size_t)(b * Nn + t * 32 + gw) * 64 + 32 + j];
    }
    __syncthreads();

    float acc[32];
    #pragma unroll
    for (int t = 0; t < 32; t++) acc[t] = 0.f;

    #pragma unroll 4
    for (int j = 0; j < 32; j++) {
        float vj = v[(size_t)(b * Nn + j * 32 + gw) * Dd + d];
        #pragma unroll
        for (int t = 0; t < 32; t++) acc[t] = fmaf(as_[t][j], vj, acc[t]);
    }
    float gm = gamma_all[layer];
    #pragma unroll
    for (int t = 0; t < 32; t++) {
        size_t idx = (size_t)(b * Nn + t * 32 + gw) * Dd + d;
        h[idx] += gm * acc[t];
    }
}

// ---------------------------------------------------------------------------
__global__ void head_k(const float* __restrict__ h, const float* __restrict__ w,
                       const float* __restrict__ bh, float* __restrict__ out)
{
    int m = blockIdx.x;
    int d = threadIdx.x;
    float p = h[(size_t)m * Dd + d] * w[d];
    #pragma unroll
    for (int o = 16; o > 0; o >>= 1) p += __shfl_xor_sync(0xFFFFFFFFu, p, o);
    __shared__ float s1[8];
    int lane = d & 31, wr = d >> 5;
    if (lane == 0) s1[wr] = p;
    __syncthreads();
    if (d == 0) {
        float S = 0;
        #pragma unroll
        for (int i = 0; i < 8; i++) S += s1[i];
        out[m] = S + bh[0];
    }
}

// ---------------------------------------------------------------------------
extern "C" void kernel_launch(void* const* d_in, const int* in_sizes, int n_in,
                              void* d_out, int out_size)
{
    const float* x       = (const float*)d_in[0];
    const float* w_patch = (const float*)d_in[1];
    const float* b_patch = (const float*)d_in[2];
    const float* pos     = (const float*)d_in[3];
    const float* w_edge  = (const float*)d_in[4];
    const float* b_edge  = (const float*)d_in[5];
    const float* ln_g    = (const float*)d_in[6];
    const float* ln_b    = (const float*)d_in[7];
    const float* wq      = (const float*)d_in[8];
    const float* bq      = (const float*)d_in[9];
    const float* wk      = (const float*)d_in[10];
    const float* bk      = (const float*)d_in[11];
    const float* wv      = (const float*)d_in[12];
    const float* bv      = (const float*)d_in[13];
    const float* gamma   = (const float*)d_in[14];
    const float* w1      = (const float*)d_in[15];
    const float* b1      = (const float*)d_in[16];
    const float* w2      = (const float*)d_in[17];
    const float* b2      = (const float*)d_in[18];
    const float* w_head  = (const float*)d_in[19];
    const float* b_head  = (const float*)d_in[20];
    float* out = (float*)d_out;

    float *im, *h, *xn, *lap, *q, *k, *v, *mid, *att, *wpT;
    cudaGetSymbolAddress((void**)&im,  g_im);
    cudaGetSymbolAddress((void**)&h,   g_h);
    cudaGetSymbolAddress((void**)&xn,  g_xn);
    cudaGetSymbolAddress((void**)&lap, g_lap);
    cudaGetSymbolAddress((void**)&q,   g_q);
    cudaGetSymbolAddress((void**)&k,   g_k);
    cudaGetSymbolAddress((void**)&v,   g_v);
    cudaGetSymbolAddress((void**)&mid, g_mid);
    cudaGetSymbolAddress((void**)&att, g_att);
    cudaGetSymbolAddress((void**)&wpT, g_wpT);

    const int M = Mtok;
    dim3 b256(256);

    // patch embed
    transpose_wp_k<<<256, b256>>>(w_patch, wpT);
    im2col_k<<<Mtok, b256>>>(x, im);
    gemm_tc<1><<<dim3(2, M / 128), b256>>>(im, wpT, b_patch, h, pos, M, Dd, Dd);

    // edge tokens: h += tanh(lap(h) @ w_edge + b_edge)
    lap_k<<<Mtok, b256>>>(h, lap);
    gemm_tc<2><<<dim3(2, M / 128), b256>>>(lap, w_edge, b_edge, h, nullptr, M, Dd, Dd);

    for (int l = 0; l < 8; l++) {
        ln_k<<<Mtok, b256>>>(h, xn, ln_g + l * Dd, ln_b + l * Dd);
        gemm_tc<0><<<dim3(1, M / 128), b256>>>(xn, wq + l * Dd * DQq, bq + l * DQq, q, nullptr, M, DQq, Dd);
        gemm_tc<0><<<dim3(1, M / 128), b256>>>(xn, wk + l * Dd * DQq, bk + l * DQq, k, nullptr, M, DQq, Dd);
        gemm_tc<0><<<dim3(2, M / 128), b256>>>(xn, wv + l * Dd * Dd,  bv + l * Dd,  v, nullptr, M, Dd, Dd);

        attn_score_k<<<Mtok / 8, b256>>>(q, k, att);
        attn_apply_row_k<<<Mtok / 32, b256>>>(att, v, xn, h, gamma, l);
        attn_apply_col_k<<<Mtok / 32, b256>>>(att, v, h, gamma, l);

        ln_k<<<Mtok, b256>>>(h, xn, ln_g + l * Dd, ln_b + l * Dd);
        gemm_tc<3><<<dim3(8, M / 128), b256>>>(xn, w1 + l * Dd * DFf, b1 + l * DFf, mid, nullptr, M, DFf, Dd);
        gemm_tc<4><<<dim3(2, M / 128), b256>>>(mid, w2 + l * DFf * Dd, b2 + l * Dd, h, nullptr, M, Dd, DFf);
    }

    head_k<<<Mtok, b256>>>(h, w_head, b_head, out);
}

// round 3
// speedup vs baseline: 2.3527x; 1.1311x over previous
#include <cuda_runtime.h>
#include <cuda_bf16.h>
#include <math.h>
#include <stdint.h>

// ---------------------------------------------------------------------------
// BoundaryAwareViT — pipelined tf32 GEMM (cp.async double-buffer) + fused QKV
// B=32, IMG=512, P=16, D=256, DEPTH=8, G=32, N=1024, DQ=32, DF=1024, M=32768
// ---------------------------------------------------------------------------

#define Mtok  32768
#define Dd    256
#define DQq   32
#define DFf   1024
#define Nn    1024
#define QKVW  320        // 32 q + 32 k + 256 v

__device__ float g_im  [Mtok * Dd];
__device__ float g_h   [Mtok * Dd];
__device__ float g_xn  [Mtok * Dd];
__device__ float g_lap [Mtok * Dd];
__device__ float g_qkv [Mtok * QKVW];
__device__ float g_mid [Mtok * DFf];
__device__ float g_att [Mtok * 64];
__device__ float g_wpT [Dd * Dd];
__device__ float g_wqkv[8 * Dd * QKVW];
__device__ float g_bqkv[8 * QKVW];

__device__ __forceinline__ uint32_t f2tf(float f) {
    uint32_t u;
    asm("cvt.rna.tf32.f32 %0, %1;" : "=r"(u) : "f"(f));
    return u;
}

// ---------------------------------------------------------------------------
// small helpers
// ---------------------------------------------------------------------------
__global__ void transpose_wp_k(const float* __restrict__ wp, float* __restrict__ out) {
    int idx = blockIdx.x * 256 + threadIdx.x;
    int d = idx >> 8, k = idx & 255;
    out[k * Dd + d] = wp[d * 256 + k];
}

__global__ void im2col_k(const float* __restrict__ x, float* __restrict__ out) {
    int idx = blockIdx.x * 256 + threadIdx.x;
    int pc  = idx & 15;
    int pr  = (idx >> 4) & 15;
    int tok = idx >> 8;
    int gw  = tok & 31, gh = (tok >> 5) & 31, b = tok >> 10;
    out[idx] = x[((b * 512) + gh * 16 + pr) * 512 + gw * 16 + pc];
}

__global__ void lap_k(const float* __restrict__ t, float* __restrict__ out) {
    int tok = blockIdx.x;
    int d   = threadIdx.x;
    int gw = tok & 31, gh = (tok >> 5) & 31;
    float c = 4.0f * t[tok * Dd + d];
    if (gh > 0)  c -= t[(tok - 32) * Dd + d];
    if (gh < 31) c -= t[(tok + 32) * Dd + d];
    if (gw > 0)  c -= t[(tok - 1) * Dd + d];
    if (gw < 31) c -= t[(tok + 1) * Dd + d];
    out[tok * Dd + d] = c;
}

// pack per-layer qkv weights: w[l][k][c] with c<32 q, c<64 k, else v
__global__ void pack_qkv_k(const float* __restrict__ wq, const float* __restrict__ wk,
                           const float* __restrict__ wv, const float* __restrict__ bq,
                           const float* __restrict__ bk, const float* __restrict__ bv,
                           float* __restrict__ w, float* __restrict__ bb)
{
    int idx = blockIdx.x * 256 + threadIdx.x;   // 8*256*320 = 655360
    int c  = idx % QKVW;
    int kk = (idx / QKVW) & 255;
    int l  = idx / (QKVW * 256);
    float val;
    if (c < 32)      val = wq[(l * 256 + kk) * 32 + c];
    else if (c < 64) val = wk[(l * 256 + kk) * 32 + (c - 32)];
    else             val = wv[(l * 256 + kk) * 256 + (c - 64)];
    w[idx] = val;
    if (idx < 8 * QKVW) {
        int l2 = idx / QKVW, c2 = idx % QKVW;
        bb[idx] = (c2 < 32) ? bq[l2 * 32 + c2]
                : (c2 < 64) ? bk[l2 * 32 + c2 - 32]
                            : bv[l2 * 256 + c2 - 64];
    }
}

// LayerNorm: one warp per token, float4, warp-shuffle reduce. 8 tokens/block.
__global__ void ln_k(const float* __restrict__ h, float* __restrict__ xn,
                     const float* __restrict__ g, const float* __restrict__ b) {
    __shared__ float sg[256], sb[256];
    int tid = threadIdx.x;
    sg[tid] = g[tid];
    sb[tid] = b[tid];
    __syncthreads();
    int warp = tid >> 5, lane = tid & 31;
    int tok = blockIdx.x * 8 + warp;
    const float* hp = h + (size_t)tok * Dd + lane * 8;
    float4 v0 = *(const float4*)hp;
    float4 v1 = *(const float4*)(hp + 4);
    float s  = v0.x + v0.y + v0.z + v0.w + v1.x + v1.y + v1.z + v1.w;
    float sq = v0.x*v0.x + v0.y*v0.y + v0.z*v0.z + v0.w*v0.w
             + v1.x*v1.x + v1.y*v1.y + v1.z*v1.z + v1.w*v1.w;
    #pragma unroll
    for (int o = 16; o > 0; o >>= 1) {
        s  += __shfl_xor_sync(0xFFFFFFFFu, s,  o);
        sq += __shfl_xor_sync(0xFFFFFFFFu, sq, o);
    }
    float mean = s * (1.0f / 256.0f);
    float var  = sq * (1.0f / 256.0f) - mean * mean;
    float rstd = rsqrtf(var + 1e-5f);
    int c0 = lane * 8;
    float4 o0, o1;
    o0.x = (v0.x - mean) * rstd * sg[c0 + 0] + sb[c0 + 0];
    o0.y = (v0.y - mean) * rstd * sg[c0 + 1] + sb[c0 + 1];
    o0.z = (v0.z - mean) * rstd * sg[c0 + 2] + sb[c0 + 2];
    o0.w = (v0.w - mean) * rstd * sg[c0 + 3] + sb[c0 + 3];
    o1.x = (v1.x - mean) * rstd * sg[c0 + 4] + sb[c0 + 4];
    o1.y = (v1.y - mean) * rstd * sg[c0 + 5] + sb[c0 + 5];
    o1.z = (v1.z - mean) * rstd * sg[c0 + 6] + sb[c0 + 6];
    o1.w = (v1.w - mean) * rstd * sg[c0 + 7] + sb[c0 + 7];
    float* xp = xn + (size_t)tok * Dd + c0;
    *(float4*)xp       = o0;
    *(float4*)(xp + 4) = o1;
}

// ---------------------------------------------------------------------------
// cp.async helpers
// ---------------------------------------------------------------------------
__device__ __forceinline__ void cp16(float* s, const float* g) {
    uint32_t sa = (uint32_t)__cvta_generic_to_shared(s);
    asm volatile("cp.async.cg.shared.global [%0], [%1], 16;" :: "r"(sa), "l"(g));
}
__device__ __forceinline__ void cp16z(float* s, const float* g, bool valid) {
    uint32_t sa = (uint32_t)__cvta_generic_to_shared(s);
    int sz = valid ? 16 : 0;
    asm volatile("cp.async.cg.shared.global [%0], [%1], 16, %2;" :: "r"(sa), "l"(g), "r"(sz));
}
#define CP_COMMIT() asm volatile("cp.async.commit_group;" ::: "memory")
#define CP_WAIT1()  asm volatile("cp.async.wait_group 1;" ::: "memory")
#define CP_WAIT0()  asm volatile("cp.async.wait_group 0;" ::: "memory")

// ---------------------------------------------------------------------------
// Pipelined tf32 GEMM: C[M,N] = A[M,K] @ B[K,N] + bias, epilogue per MODE.
// 128x128x32 tiles, 2-stage cp.async double buffer, 8 warps, m16n8k8 mma.
//   MODE 0: C = val;  1: C = val + pos;  2: C += tanh(val);
//   MODE 3: C = gelu(val);  4: C += val
// M%128==0, K%32==0; N%4==0 (guarded per 16B chunk / per element).
// Dynamic smem: 2*(128*36 + 32*136)*4 = 71680 bytes.
// ---------------------------------------------------------------------------
#define AS_STRIDE 36
#define BS_STRIDE 136
#define A_STAGE (128 * AS_STRIDE)
#define B_STAGE (32 * BS_STRIDE)

template<int MODE>
__global__ void __launch_bounds__(256)
gemm_tc(const float* __restrict__ A, const float* __restrict__ Bm,
        const float* __restrict__ bias, float* __restrict__ C,
        const float* __restrict__ extra, int M, int N, int K)
{
    extern __shared__ float sm[];
    float* As = sm;                       // [2][128][36]
    float* Bs = sm + 2 * A_STAGE;         // [2][32][136]

    const int tid  = threadIdx.x;
    const int warp = tid >> 5, lane = tid & 31;
    const int wm = warp >> 2, wn = warp & 3;
    const int row0 = blockIdx.y * 128, col0 = blockIdx.x * 128;
    const int g = lane >> 2, tg = lane & 3;

    // per-thread load coords
    const int ar = tid >> 1;              // 0..127
    const int ac = (tid & 1) * 16;        // unused; we use 4-chunk scheme below

    float acc[4][4][4];
    #pragma unroll
    for (int i = 0; i < 4; i++)
        #pragma unroll
        for (int j = 0; j < 4; j++)
            #pragma unroll
            for (int e = 0; e < 4; e++) acc[i][j][e] = 0.0f;

    auto load_tile = [&](int stage, int k0) {
        float* as = As + stage * A_STAGE;
        float* bs = Bs + stage * B_STAGE;
        #pragma unroll
        for (int i = 0; i < 4; i++) {
            int idx = tid + i * 256;
            int r = idx >> 3, c = (idx & 7) * 4;
            cp16(as + r * AS_STRIDE + c, A + (size_t)(row0 + r) * K + k0 + c);
        }
        #pragma unroll
        for (int i = 0; i < 4; i++) {
            int idx = tid + i * 256;
            int r = idx >> 5, c = (idx & 31) * 4;
            cp16z(bs + r * BS_STRIDE + c, Bm + (size_t)(k0 + r) * N + col0 + c,
                  (col0 + c) < N);
        }
    };

    const int ntiles = K >> 5;
    load_tile(0, 0);
    CP_COMMIT();

    for (int t = 0; t < ntiles; t++) {
        int cur = t & 1;
        if (t + 1 < ntiles) {
            load_tile(cur ^ 1, (t + 1) << 5);
            CP_COMMIT();
            CP_WAIT1();
        } else {
            CP_WAIT0();
        }
        __syncthreads();

        const float* as = As + cur * A_STAGE;
        const float* bs = Bs + cur * B_STAGE;
        #pragma unroll
        for (int kk = 0; kk < 4; kk++) {
            const int kb = kk * 8;
            uint32_t af[4][4], bf[4][2];
            #pragma unroll
            for (int mi = 0; mi < 4; mi++) {
                int m0 = wm * 64 + mi * 16;
                af[mi][0] = f2tf(as[(m0 + g    ) * AS_STRIDE + kb + tg    ]);
                af[mi][1] = f2tf(as[(m0 + 8 + g) * AS_STRIDE + kb + tg    ]);
                af[mi][2] = f2tf(as[(m0 + g    ) * AS_STRIDE + kb + 4 + tg]);
                af[mi][3] = f2tf(as[(m0 + 8 + g) * AS_STRIDE + kb + 4 + tg]);
            }
            #pragma unroll
            for (int nj = 0; nj < 4; nj++) {
                int n0 = wn * 32 + nj * 8;
                bf[nj][0] = f2tf(bs[(kb + tg    ) * BS_STRIDE + n0 + g]);
                bf[nj][1] = f2tf(bs[(kb + 4 + tg) * BS_STRIDE + n0 + g]);
            }
            #pragma unroll
            for (int mi = 0; mi < 4; mi++)
                #pragma unroll
                for (int nj = 0; nj < 4; nj++)
                    asm volatile(
                        "mma.sync.aligned.m16n8k8.row.col.f32.tf32.tf32.f32 "
                        "{%0,%1,%2,%3}, {%4,%5,%6,%7}, {%8,%9}, {%0,%1,%2,%3};"
                        : "+f"(acc[mi][nj][0]), "+f"(acc[mi][nj][1]),
                          "+f"(acc[mi][nj][2]), "+f"(acc[mi][nj][3])
                        : "r"(af[mi][0]), "r"(af[mi][1]),
                          "r"(af[mi][2]), "r"(af[mi][3]),
                          "r"(bf[nj][0]), "r"(bf[nj][1]));
        }
        __syncthreads();
    }
    (void)ar; (void)ac;

    #pragma unroll
    for (int mi = 0; mi < 4; mi++) {
        #pragma unroll
        for (int nj = 0; nj < 4; nj++) {
            int r0 = row0 + wm * 64 + mi * 16 + g;
            int c0 = col0 + wn * 32 + nj * 8 + tg * 2;
            #pragma unroll
            for (int e = 0; e < 4; e++) {
                int r = r0 + (e >> 1) * 8;
                int c = c0 + (e & 1);
                if (c < N) {
                    float val = acc[mi][nj][e] + bias[c];
                    size_t idx = (size_t)r * N + c;
                    if (MODE == 0) {
                        C[idx] = val;
                    } else if (MODE == 1) {
                        C[idx] = val + extra[(size_t)(r & 1023) * N + c];
                    } else if (MODE == 2) {
                        C[idx] += tanhf(val);
                    } else if (MODE == 3) {
                        C[idx] = val * 0.5f * (1.0f + erff(val * 0.70710678118654752f));
                    } else {
                        C[idx] += val;
                    }
                }
            }
        }
    }
}

// ---------------------------------------------------------------------------
// Attention scores + softmax: one warp per token -> att[tok][64]
// q = qkv[tok][0:32], k = qkv[tok][32:64]
// ---------------------------------------------------------------------------
__global__ void attn_score_k(const float* __restrict__ qkv, float* __restrict__ att)
{
    int warp = threadIdx.x >> 5;
    int lane = threadIdx.x & 31;
    int tok = blockIdx.x * 8 + warp;
    int gw = tok & 31, gh = (tok >> 5) & 31, b = tok >> 10;

    __shared__ float qs[8][32];
    qs[warp][lane] = qkv[(size_t)tok * QKVW + lane];
    __syncwarp();

    const float* krow = qkv + (size_t)(b * Nn + gh * 32 + lane) * QKVW + 32;
    const float* kcol = qkv + (size_t)(b * Nn + lane * 32 + gw) * QKVW + 32;
    float sr = 0.f, sc = 0.f;
    #pragma unroll
    for (int c = 0; c < 32; c += 4) {
        float4 kr = *(const float4*)(krow + c);
        float4 kc = *(const float4*)(kcol + c);
        float q0 = qs[warp][c], q1 = qs[warp][c + 1], q2 = qs[warp][c + 2], q3 = qs[warp][c + 3];
        sr = fmaf(q0, kr.x, fmaf(q1, kr.y, fmaf(q2, kr.z, fmaf(q3, kr.w, sr))));
        sc = fmaf(q0, kc.x, fmaf(q1, kc.y, fmaf(q2, kc.z, fmaf(q3, kc.w, sc))));
    }
    const float scale = 0.17677669529663687f;   // 1/sqrt(32)
    sr *= scale;
    sc *= scale;
    if (lane == gh) sc -= 1e9f;

    float m2 = fmaxf(sr, sc);
    #pragma unroll
    for (int o = 16; o > 0; o >>= 1) m2 = fmaxf(m2, __shfl_xor_sync(0xFFFFFFFFu, m2, o));
    float e0 = expf(sr - m2), e1 = expf(sc - m2);
    float s = e0 + e1;
    #pragma unroll
    for (int o = 16; o > 0; o >>= 1) s += __shfl_xor_sync(0xFFFFFFFFu, s, o);
    float inv = 1.0f / s;
    att[(size_t)tok * 64 + lane]      = e0 * inv;
    att[(size_t)tok * 64 + 32 + lane] = e1 * inv;
}

// ---------------------------------------------------------------------------
// Apply row attention: block = (b, gh); h += xn + gamma * out_row
// v = qkv[.][64:320]
// ---------------------------------------------------------------------------
__global__ void attn_apply_row_k(const float* __restrict__ att, const float* __restrict__ qkv,
                                 const float* __restrict__ xn, float* __restrict__ h,
                                 const float* __restrict__ gamma_all, int layer)
{
    int blk = blockIdx.x;
    int b = blk >> 5, gh = blk & 31;
    int d = threadIdx.x;
    int base_tok = b * Nn + gh * 32;

    __shared__ float as_[32][32];
    for (int i = d; i < 1024; i += 256) {
        int t = i >> 5, j = i & 31;
        as_[t][j] = att[(size_t)(base_tok + t) * 64 + j];
    }
    __syncthreads();

    float acc[32];
    #pragma unroll
    for (int t = 0; t < 32; t++) acc[t] = 0.f;

    const float* vp = qkv + (size_t)base_tok * QKVW + 64 + d;
    #pragma unroll 4
    for (int j = 0; j < 32; j++) {
        float vj = vp[j * QKVW];
        #pragma unroll
        for (int t = 0; t < 32; t++) acc[t] = fmaf(as_[t][j], vj, acc[t]);
    }
    float gm = gamma_all[layer];
    #pragma unroll
    for (int t = 0; t < 32; t++) {
        size_t idx = (size_t)(base_tok + t) * Dd + d;
        h[idx] += xn[idx] + gm * acc[t];
    }
}

// ---------------------------------------------------------------------------
// Apply column attention: block = (b, gw); h += gamma * out_col
// ---------------------------------------------------------------------------
__global__ void attn_apply_col_k(const float* __restrict__ att, const float* __restrict__ qkv,
                                 float* __restrict__ h,
                                 const float* __restrict__ gamma_all, int layer)
{
    int blk = blockIdx.x;
    int b = blk >> 5, gw = blk & 31;
    int d = threadIdx.x;

    __shared__ float as_[32][32];
    for (int i = d; i < 1024; i += 256) {
        int t = i >> 5, j = i & 31;
        as_[t][j] = att[(size_t)(b * Nn + t * 32 + gw) * 64 + 32 + j];
    }
    __syncthreads();

    float acc[32];
    #pragma unroll
    for (int t = 0; t < 32; t++) acc[t] = 0.f;

    #pragma unroll 4
    for (int j = 0; j < 32; j++) {
        float vj = qkv[(size_t)(b * Nn + j * 32 + gw) * QKVW + 64 + d];
        #pragma unroll
        for (int t = 0; t < 32; t++) acc[t] = fmaf(as_[t][j], vj, acc[t]);
    }
    float gm = gamma_all[layer];
    #pragma unroll
    for (int t = 0; t < 32; t++) {
        size_t idx = (size_t)(b * Nn + t * 32 + gw) * Dd + d;
        h[idx] += gm * acc[t];
    }
}

// ---------------------------------------------------------------------------
__global__ void head_k(const float* __restrict__ h, const float* __restrict__ w,
                       const float* __restrict__ bh, float* __restrict__ out)
{
    int m = blockIdx.x;
    int d = threadIdx.x;
    float p = h[(size_t)m * Dd + d] * w[d];
    #pragma unroll
    for (int o = 16; o > 0; o >>= 1) p += __shfl_xor_sync(0xFFFFFFFFu, p, o);
    __shared__ float s1[8];
    int lane = d & 31, wr = d >> 5;
    if (lane == 0) s1[wr] = p;
    __syncthreads();
    if (d == 0) {
        float S = 0;
        #pragma unroll
        for (int i = 0; i < 8; i++) S += s1[i];
        out[m] = S + bh[0];
    }
}

// ---------------------------------------------------------------------------
extern "C" void kernel_launch(void* const* d_in, const int* in_sizes, int n_in,
                              void* d_out, int out_size)
{
    const float* x       = (const float*)d_in[0];
    const float* w_patch = (const float*)d_in[1];
    const float* b_patch = (const float*)d_in[2];
    const float* pos     = (const float*)d_in[3];
    const float* w_edge  = (const float*)d_in[4];
    const float* b_edge  = (const float*)d_in[5];
    const float* ln_g    = (const float*)d_in[6];
    const float* ln_b    = (const float*)d_in[7];
    const float* wq      = (const float*)d_in[8];
    const float* bq      = (const float*)d_in[9];
    const float* wk      = (const float*)d_in[10];
    const float* bk      = (const float*)d_in[11];
    const float* wv      = (const float*)d_in[12];
    const float* bv      = (const float*)d_in[13];
    const float* gamma   = (const float*)d_in[14];
    const float* w1      = (const float*)d_in[15];
    const float* b1      = (const float*)d_in[16];
    const float* w2      = (const float*)d_in[17];
    const float* b2      = (const float*)d_in[18];
    const float* w_head  = (const float*)d_in[19];
    const float* b_head  = (const float*)d_in[20];
    float* out = (float*)d_out;

    float *im, *h, *xn, *lap, *qkv, *mid, *att, *wpT, *wqkv, *bqkv;
    cudaGetSymbolAddress((void**)&im,   g_im);
    cudaGetSymbolAddress((void**)&h,    g_h);
    cudaGetSymbolAddress((void**)&xn,   g_xn);
    cudaGetSymbolAddress((void**)&lap,  g_lap);
    cudaGetSymbolAddress((void**)&qkv,  g_qkv);
    cudaGetSymbolAddress((void**)&mid,  g_mid);
    cudaGetSymbolAddress((void**)&att,  g_att);
    cudaGetSymbolAddress((void**)&wpT,  g_wpT);
    cudaGetSymbolAddress((void**)&wqkv, g_wqkv);
    cudaGetSymbolAddress((void**)&bqkv, g_bqkv);

    const int SMEM = (2 * A_STAGE + 2 * B_STAGE) * 4;   // 71680 bytes
    static bool attr_done = false;
    if (!attr_done) {
        cudaFuncSetAttribute(gemm_tc<0>, cudaFuncAttributeMaxDynamicSharedMemorySize, SMEM);
        cudaFuncSetAttribute(gemm_tc<1>, cudaFuncAttributeMaxDynamicSharedMemorySize, SMEM);
        cudaFuncSetAttribute(gemm_tc<2>, cudaFuncAttributeMaxDynamicSharedMemorySize, SMEM);
        cudaFuncSetAttribute(gemm_tc<3>, cudaFuncAttributeMaxDynamicSharedMemorySize, SMEM);
        cudaFuncSetAttribute(gemm_tc<4>, cudaFuncAttributeMaxDynamicSharedMemorySize, SMEM);
        attr_done = true;
    }

    const int M = Mtok;
    dim3 b256(256);

    // setup
    transpose_wp_k<<<256, b256>>>(w_patch, wpT);
    im2col_k<<<Mtok, b256>>>(x, im);
    pack_qkv_k<<<2560, b256>>>(wq, wk, wv, bq, bk, bv, wqkv, bqkv);

    // patch embed
    gemm_tc<1><<<dim3(2, M / 128), b256, SMEM>>>(im, wpT, b_patch, h, pos, M, Dd, Dd);

    // edge tokens: h += tanh(lap(h) @ w_edge + b_edge)
    lap_k<<<Mtok, b256>>>(h, lap);
    gemm_tc<2><<<dim3(2, M / 128), b256, SMEM>>>(lap, w_edge, b_edge, h, nullptr, M, Dd, Dd);

    for (int l = 0; l < 8; l++) {
        ln_k<<<Mtok / 8, b256>>>(h, xn, ln_g + l * Dd, ln_b + l * Dd);
        gemm_tc<0><<<dim3(3, M / 128), b256, SMEM>>>(xn, wqkv + (size_t)l * Dd * QKVW,
                                                     bqkv + l * QKVW, qkv, nullptr, M, QKVW, Dd);
        attn_score_k<<<Mtok / 8, b256>>>(qkv, att);
        attn_apply_row_k<<<Mtok / 32, b256>>>(att, qkv, xn, h, gamma, l);
        attn_apply_col_k<<<Mtok / 32, b256>>>(att, qkv, h, gamma, l);

        ln_k<<<Mtok / 8, b256>>>(h, xn, ln_g + l * Dd, ln_b + l * Dd);
        gemm_tc<3><<<dim3(8, M / 128), b256, SMEM>>>(xn, w1 + (size_t)l * Dd * DFf,
                                                     b1 + l * DFf, mid, nullptr, M, DFf, Dd);
        gemm_tc<4><<<dim3(2, M / 128), b256, SMEM>>>(mid, w2 + (size_t)l * DFf * Dd,
                                                     b2 + l * Dd, h, nullptr, M, Dd, DFf);
    }

    head_k<<<Mtok, b256>>>(h, w_head, b_head, out);
}

// round 4
// speedup vs baseline: 2.3633x; 1.0045x over previous
#include <cuda_runtime.h>
#include <cuda_bf16.h>
#include <math.h>
#include <stdint.h>

// ---------------------------------------------------------------------------
// BoundaryAwareViT — tf32 GEMM w/ ldmatrix fragments + transposed weights.
// B=32, IMG=512, P=16, D=256, DEPTH=8, G=32, N=1024, DQ=32, DF=1024, M=32768
// ---------------------------------------------------------------------------

#define Mtok  32768
#define Dd    256
#define DFf   1024
#define Nn    1024
#define QKVW  320        // 32 q + 32 k + 256 v

__device__ float g_im  [Mtok * Dd];
__device__ float g_h   [Mtok * Dd];
__device__ float g_xn  [Mtok * Dd];
__device__ float g_lap [Mtok * Dd];
__device__ float g_qkv [Mtok * QKVW];
__device__ float g_mid [Mtok * DFf];
__device__ float g_att [Mtok * 64];
__device__ float g_wpT [Dd * Dd];          // patch weight [n][k], rounded
__device__ float g_weT [Dd * Dd];          // edge weight transposed [n][k]
__device__ float g_wqkvT[8 * QKVW * Dd];   // [l][c][k]
__device__ float g_bqkv [8 * QKVW];
__device__ float g_w1T [8 * DFf * Dd];     // [l][1024][256]
__device__ float g_w2T [8 * Dd * DFf];     // [l][256][1024]

__device__ __forceinline__ uint32_t f2tf(float f) {
    uint32_t u;
    asm("cvt.rna.tf32.f32 %0, %1;" : "=r"(u) : "f"(f));
    return u;
}
__device__ __forceinline__ float rndtf(float f) { return __uint_as_float(f2tf(f)); }

// ---------------------------------------------------------------------------
// prep kernels (tiny, once per launch)
// ---------------------------------------------------------------------------
__global__ void round_copy_k(const float* __restrict__ src, float* __restrict__ dst, int n) {
    int i = blockIdx.x * 256 + threadIdx.x;
    if (i < n) dst[i] = rndtf(src[i]);
}

// batched transpose + tf32 round: src [L][R][C] -> dst [L][C][R]
__global__ void transpose_rnd_k(const float* __restrict__ src, float* __restrict__ dst,
                                int R, int C) {
    __shared__ float t[32][33];
    int l = blockIdx.z;
    const float* s = src + (size_t)l * R * C;
    float* d = dst + (size_t)l * R * C;
    int c0 = blockIdx.x * 32, r0 = blockIdx.y * 32;
    int tx = threadIdx.x & 31, ty = threadIdx.x >> 5;    // 256 thr: ty 0..7
    #pragma unroll
    for (int i = 0; i < 32; i += 8)
        t[ty + i][tx] = s[(size_t)(r0 + ty + i) * C + c0 + tx];
    __syncthreads();
    #pragma unroll
    for (int i = 0; i < 32; i += 8)
        d[(size_t)(c0 + ty + i) * R + r0 + tx] = rndtf(t[tx][ty + i]);
}

// pack qkv weights transposed: dst[l][c][k], c<32 q, c<64 k, else v. rounded.
__global__ void pack_qkvT_k(const float* __restrict__ wq, const float* __restrict__ wk,
                            const float* __restrict__ wv, const float* __restrict__ bq,
                            const float* __restrict__ bk, const float* __restrict__ bv,
                            float* __restrict__ w, float* __restrict__ bb)
{
    int idx = blockIdx.x * 256 + threadIdx.x;   // 8*320*256
    int k  = idx & 255;
    int c  = (idx >> 8) % QKVW;
    int l  = idx / (QKVW * 256);
    float val;
    if (c < 32)      val = wq[(l * 256 + k) * 32 + c];
    else if (c < 64) val = wk[(l * 256 + k) * 32 + (c - 32)];
    else             val = wv[(l * 256 + k) * 256 + (c - 64)];
    w[idx] = rndtf(val);
    if (idx < 8 * QKVW) {
        int l2 = idx / QKVW, c2 = idx % QKVW;
        bb[idx] = (c2 < 32) ? bq[l2 * 32 + c2]
                : (c2 < 64) ? bk[l2 * 32 + c2 - 32]
                            : bv[l2 * 256 + c2 - 64];
    }
}

// ---------------------------------------------------------------------------
// small helpers
// ---------------------------------------------------------------------------
__global__ void im2col_k(const float* __restrict__ x, float* __restrict__ out) {
    int idx = blockIdx.x * 256 + threadIdx.x;
    int pc  = idx & 15;
    int pr  = (idx >> 4) & 15;
    int tok = idx >> 8;
    int gw  = tok & 31, gh = (tok >> 5) & 31, b = tok >> 10;
    out[idx] = rndtf(x[((b * 512) + gh * 16 + pr) * 512 + gw * 16 + pc]);
}

__global__ void lap_k(const float* __restrict__ t, float* __restrict__ out) {
    int tok = blockIdx.x;
    int d   = threadIdx.x;
    int gw = tok & 31, gh = (tok >> 5) & 31;
    float c = 4.0f * t[tok * Dd + d];
    if (gh > 0)  c -= t[(tok - 32) * Dd + d];
    if (gh < 31) c -= t[(tok + 32) * Dd + d];
    if (gw > 0)  c -= t[(tok - 1) * Dd + d];
    if (gw < 31) c -= t[(tok + 1) * Dd + d];
    out[tok * Dd + d] = rndtf(c);
}

// LayerNorm: one warp per token, float4, warp-shuffle reduce. 8 tokens/block.
__global__ void ln_k(const float* __restrict__ h, float* __restrict__ xn,
                     const float* __restrict__ g, const float* __restrict__ b) {
    __shared__ float sg[256], sb[256];
    int tid = threadIdx.x;
    sg[tid] = g[tid];
    sb[tid] = b[tid];
    __syncthreads();
    int warp = tid >> 5, lane = tid & 31;
    int tok = blockIdx.x * 8 + warp;
    const float* hp = h + (size_t)tok * Dd + lane * 8;
    float4 v0 = *(const float4*)hp;
    float4 v1 = *(const float4*)(hp + 4);
    float s  = v0.x + v0.y + v0.z + v0.w + v1.x + v1.y + v1.z + v1.w;
    float sq = v0.x*v0.x + v0.y*v0.y + v0.z*v0.z + v0.w*v0.w
             + v1.x*v1.x + v1.y*v1.y + v1.z*v1.z + v1.w*v1.w;
    #pragma unroll
    for (int o = 16; o > 0; o >>= 1) {
        s  += __shfl_xor_sync(0xFFFFFFFFu, s,  o);
        sq += __shfl_xor_sync(0xFFFFFFFFu, sq, o);
    }
    float mean = s * (1.0f / 256.0f);
    float var  = sq * (1.0f / 256.0f) - mean * mean;
    float rstd = rsqrtf(var + 1e-5f);
    int c0 = lane * 8;
    float4 o0, o1;
    o0.x = (v0.x - mean) * rstd * sg[c0 + 0] + sb[c0 + 0];
    o0.y = (v0.y - mean) * rstd * sg[c0 + 1] + sb[c0 + 1];
    o0.z = (v0.z - mean) * rstd * sg[c0 + 2] + sb[c0 + 2];
    o0.w = (v0.w - mean) * rstd * sg[c0 + 3] + sb[c0 + 3];
    o1.x = (v1.x - mean) * rstd * sg[c0 + 4] + sb[c0 + 4];
    o1.y = (v1.y - mean) * rstd * sg[c0 + 5] + sb[c0 + 5];
    o1.z = (v1.z - mean) * rstd * sg[c0 + 6] + sb[c0 + 6];
    o1.w = (v1.w - mean) * rstd * sg[c0 + 7] + sb[c0 + 7];
    float* xp = xn + (size_t)tok * Dd + c0;
    *(float4*)xp       = o0;
    *(float4*)(xp + 4) = o1;
}

// ---------------------------------------------------------------------------
// cp.async helpers
// ---------------------------------------------------------------------------
__device__ __forceinline__ void cp16(float* s, const float* g) {
    uint32_t sa = (uint32_t)__cvta_generic_to_shared(s);
    asm volatile("cp.async.cg.shared.global [%0], [%1], 16;" :: "r"(sa), "l"(g));
}
__device__ __forceinline__ void cp16z(float* s, const float* g, bool valid) {
    uint32_t sa = (uint32_t)__cvta_generic_to_shared(s);
    int sz = valid ? 16 : 0;
    asm volatile("cp.async.cg.shared.global [%0], [%1], 16, %2;" :: "r"(sa), "l"(g), "r"(sz));
}
#define CP_COMMIT() asm volatile("cp.async.commit_group;" ::: "memory")
#define CP_WAIT1()  asm volatile("cp.async.wait_group 1;" ::: "memory")
#define CP_WAIT0()  asm volatile("cp.async.wait_group 0;" ::: "memory")

__device__ __forceinline__ void ldsm4(uint32_t& r0, uint32_t& r1, uint32_t& r2, uint32_t& r3,
                                      uint32_t addr) {
    asm volatile("ldmatrix.sync.aligned.m8n8.x4.shared.b16 {%0,%1,%2,%3}, [%4];"
                 : "=r"(r0), "=r"(r1), "=r"(r2), "=r"(r3) : "r"(addr));
}

// ---------------------------------------------------------------------------
// tf32 GEMM: C[M,N] = A[M,K] @ BT[N,K]^T + bias. 128x128x32 tiles, 2-stage
// cp.async, ldmatrix fragment loads (BT row-major => non-trans ldsm).
//   MODE 0: C=val; 1: C=val+pos; 2: C+=tanh(val); 3: C=gelu(val) (rounded);
//   MODE 4: C+=val
// CVTA: round A fragments to tf32 at load (A not pre-rounded, e.g. xn).
// BT rows guarded (zfill) for N=320. Dyn smem: 2*2*128*36*4 = 73728 B.
// ---------------------------------------------------------------------------
#define TS_STRIDE 36
#define T_STAGE (128 * TS_STRIDE)

template<int MODE, int CVTA>
__global__ void __launch_bounds__(256, 2)
gemm_tc(const float* __restrict__ A, const float* __restrict__ BT,
        const float* __restrict__ bias, float* __restrict__ C,
        const float* __restrict__ extra, int M, int N, int K)
{
    extern __shared__ float sm[];
    float* As = sm;                       // [2][128][36]
    float* Bs = sm + 2 * T_STAGE;         // [2][128][36]

    const int tid  = threadIdx.x;
    const int warp = tid >> 5, lane = tid & 31;
    const int wm = warp >> 2, wn = warp & 3;
    const int row0 = blockIdx.y * 128, col0 = blockIdx.x * 128;
    const int g = lane >> 2, tg = lane & 3;
    const int lr = lane & 7, sel = lane >> 3;

    float acc[4][4][4];
    #pragma unroll
    for (int i = 0; i < 4; i++)
        #pragma unroll
        for (int j = 0; j < 4; j++)
            #pragma unroll
            for (int e = 0; e < 4; e++) acc[i][j][e] = 0.0f;

    auto load_tile = [&](int stage, int k0) {
        float* as = As + stage * T_STAGE;
        float* bs = Bs + stage * T_STAGE;
        #pragma unroll
        for (int i = 0; i < 4; i++) {
            int idx = tid + i * 256;
            int r = idx >> 3, c = (idx & 7) * 4;
            cp16(as + r * TS_STRIDE + c, A + (size_t)(row0 + r) * K + k0 + c);
        }
        #pragma unroll
        for (int i = 0; i < 4; i++) {
            int idx = tid + i * 256;
            int r = idx >> 3, c = (idx & 7) * 4;
            cp16z(bs + r * TS_STRIDE + c, BT + (size_t)(col0 + r) * K + k0 + c,
                  (col0 + r) < N);
        }
    };

    // ldmatrix byte offsets (within a stage), fixed per thread:
    //   A matrix sel: 0:(+0,kb) 1:(+8,kb) 2:(+0,kb+4) 3:(+8,kb+4)
    uint32_t a_off[4], b_off[2];
    #pragma unroll
    for (int mi = 0; mi < 4; mi++) {
        int r = wm * 64 + mi * 16 + lr + (sel & 1) * 8;
        a_off[mi] = (uint32_t)((r * TS_STRIDE + (sel >> 1) * 4) * 4);
    }
    //   B matrix sel: 0:(n0+lr,kb) 1:(n0+lr,kb+4) 2:(n0+8+lr,kb) 3:(n0+8+lr,kb+4)
    #pragma unroll
    for (int njp = 0; njp < 2; njp++) {
        int r = wn * 32 + njp * 16 + lr + (sel >> 1) * 8;
        b_off[njp] = (uint32_t)((r * TS_STRIDE + (sel & 1) * 4) * 4);
    }

    const uint32_t as_base = (uint32_t)__cvta_generic_to_shared(As);
    const uint32_t bs_base = (uint32_t)__cvta_generic_to_shared(Bs);

    const int ntiles = K >> 5;
    load_tile(0, 0);
    CP_COMMIT();

    for (int t = 0; t < ntiles; t++) {
        int cur = t & 1;
        if (t + 1 < ntiles) {
            load_tile(cur ^ 1, (t + 1) << 5);
            CP_COMMIT();
            CP_WAIT1();
        } else {
            CP_WAIT0();
        }
        __syncthreads();

        uint32_t as_st = as_base + cur * (T_STAGE * 4);
        uint32_t bs_st = bs_base + cur * (T_STAGE * 4);
        #pragma unroll
        for (int kk = 0; kk < 4; kk++) {
            const uint32_t kboff = (uint32_t)(kk * 8 * 4);
            uint32_t af[4][4], bf[4][2];
            #pragma unroll
            for (int mi = 0; mi < 4; mi++) {
                ldsm4(af[mi][0], af[mi][1], af[mi][2], af[mi][3],
                      as_st + a_off[mi] + kboff);
                if (CVTA) {
                    #pragma unroll
                    for (int e = 0; e < 4; e++)
                        af[mi][e] = f2tf(__uint_as_float(af[mi][e]));
                }
            }
            #pragma unroll
            for (int njp = 0; njp < 2; njp++)
                ldsm4(bf[2*njp][0], bf[2*njp][1], bf[2*njp+1][0], bf[2*njp+1][1],
                      bs_st + b_off[njp] + kboff);

            #pragma unroll
            for (int mi = 0; mi < 4; mi++)
                #pragma unroll
                for (int nj = 0; nj < 4; nj++)
                    asm volatile(
                        "mma.sync.aligned.m16n8k8.row.col.f32.tf32.tf32.f32 "
                        "{%0,%1,%2,%3}, {%4,%5,%6,%7}, {%8,%9}, {%0,%1,%2,%3};"
                        : "+f"(acc[mi][nj][0]), "+f"(acc[mi][nj][1]),
                          "+f"(acc[mi][nj][2]), "+f"(acc[mi][nj][3])
                        : "r"(af[mi][0]), "r"(af[mi][1]),
                          "r"(af[mi][2]), "r"(af[mi][3]),
                          "r"(bf[nj][0]), "r"(bf[nj][1]));
        }
        __syncthreads();
    }

    #pragma unroll
    for (int mi = 0; mi < 4; mi++) {
        #pragma unroll
        for (int nj = 0; nj < 4; nj++) {
            int r0 = row0 + wm * 64 + mi * 16 + g;
            int c0 = col0 + wn * 32 + nj * 8 + tg * 2;
            #pragma unroll
            for (int e = 0; e < 4; e++) {
                int r = r0 + (e >> 1) * 8;
                int c = c0 + (e & 1);
                if (c < N) {
                    float val = acc[mi][nj][e] + bias[c];
                    size_t idx = (size_t)r * N + c;
                    if (MODE == 0) {
                        C[idx] = val;
                    } else if (MODE == 1) {
                        C[idx] = val + extra[(size_t)(r & 1023) * N + c];
                    } else if (MODE == 2) {
                        C[idx] += tanhf(val);
                    } else if (MODE == 3) {
                        C[idx] = rndtf(val * 0.5f * (1.0f + erff(val * 0.70710678118654752f)));
                    } else {
                        C[idx] += val;
                    }
                }
            }
        }
    }
}

// ---------------------------------------------------------------------------
// Attention scores + softmax: one warp per token -> att[tok][64]
// ---------------------------------------------------------------------------
__global__ void attn_score_k(const float* __restrict__ qkv, float* __restrict__ att)
{
    int warp = threadIdx.x >> 5;
    int lane = threadIdx.x & 31;
    int tok = blockIdx.x * 8 + warp;
    int gw = tok & 31, gh = (tok >> 5) & 31, b = tok >> 10;

    __shared__ float qs[8][32];
    qs[warp][lane] = qkv[(size_t)tok * QKVW + lane];
    __syncwarp();

    const float* krow = qkv + (size_t)(b * Nn + gh * 32 + lane) * QKVW + 32;
    const float* kcol = qkv + (size_t)(b * Nn + lane * 32 + gw) * QKVW + 32;
    float sr = 0.f, sc = 0.f;
    #pragma unroll
    for (int c = 0; c < 32; c += 4) {
        float4 kr = *(const float4*)(krow + c);
        float4 kc = *(const float4*)(kcol + c);
        float q0 = qs[warp][c], q1 = qs[warp][c + 1], q2 = qs[warp][c + 2], q3 = qs[warp][c + 3];
        sr = fmaf(q0, kr.x, fmaf(q1, kr.y, fmaf(q2, kr.z, fmaf(q3, kr.w, sr))));
        sc = fmaf(q0, kc.x, fmaf(q1, kc.y, fmaf(q2, kc.z, fmaf(q3, kc.w, sc))));
    }
    const float scale = 0.17677669529663687f;   // 1/sqrt(32)
    sr *= scale;
    sc *= scale;
    if (lane == gh) sc -= 1e9f;

    float m2 = fmaxf(sr, sc);
    #pragma unroll
    for (int o = 16; o > 0; o >>= 1) m2 = fmaxf(m2, __shfl_xor_sync(0xFFFFFFFFu, m2, o));
    float e0 = expf(sr - m2), e1 = expf(sc - m2);
    float s = e0 + e1;
    #pragma unroll
    for (int o = 16; o > 0; o >>= 1) s += __shfl_xor_sync(0xFFFFFFFFu, s, o);
    float inv = 1.0f / s;
    att[(size_t)tok * 64 + lane]      = e0 * inv;
    att[(size_t)tok * 64 + 32 + lane] = e1 * inv;
}

// ---------------------------------------------------------------------------
// Apply row attention: block = (b, gh); h += xn + gamma * out_row
// ---------------------------------------------------------------------------
__global__ void attn_apply_row_k(const float* __restrict__ att, const float* __restrict__ qkv,
                                 const float* __restrict__ xn, float* __restrict__ h,
                                 const float* __restrict__ gamma_all, int layer)
{
    int blk = blockIdx.x;
    int b = blk >> 5, gh = blk & 31;
    int d = threadIdx.x;
    int base_tok = b * Nn + gh * 32;

    __shared__ float as_[32][32];
    for (int i = d; i < 1024; i += 256) {
        int t = i >> 5, j = i & 31;
        as_[t][j] = att[(size_t)(base_tok + t) * 64 + j];
    }
    __syncthreads();

    float acc[32];
    #pragma unroll
    for (int t = 0; t < 32; t++) acc[t] = 0.f;

    const float* vp = qkv + (size_t)base_tok * QKVW + 64 + d;
    #pragma unroll 4
    for (int j = 0; j < 32; j++) {
        float vj = vp[j * QKVW];
        #pragma unroll
        for (int t = 0; t < 32; t++) acc[t] = fmaf(as_[t][j], vj, acc[t]);
    }
    float gm = gamma_all[layer];
    #pragma unroll
    for (int t = 0; t < 32; t++) {
        size_t idx = (size_t)(base_tok + t) * Dd + d;
        h[idx] += xn[idx] + gm * acc[t];
    }
}

// ---------------------------------------------------------------------------
// Apply column attention: block = (b, gw); h += gamma * out_col
// ---------------------------------------------------------------------------
__global__ void attn_apply_col_k(const float* __restrict__ att, const float* __restrict__ qkv,
                                 float* __restrict__ h,
                                 const float* __restrict__ gamma_all, int layer)
{
    int blk = blockIdx.x;
    int b = blk >> 5, gw = blk & 31;
    int d = threadIdx.x;

    __shared__ float as_[32][32];
    for (int i = d; i < 1024; i += 256) {
        int t = i >> 5, j = i & 31;
        as_[t][j] = att[(size_t)(b * Nn + t * 32 + gw) * 64 + 32 + j];
    }
    __syncthreads();

    float acc[32];
    #pragma unroll
    for (int t = 0; t < 32; t++) acc[t] = 0.f;

    #pragma unroll 4
    for (int j = 0; j < 32; j++) {
        float vj = qkv[(size_t)(b * Nn + j * 32 + gw) * QKVW + 64 + d];
        #pragma unroll
        for (int t = 0; t < 32; t++) acc[t] = fmaf(as_[t][j], vj, acc[t]);
    }
    float gm = gamma_all[layer];
    #pragma unroll
    for (int t = 0; t < 32; t++) {
        size_t idx = (size_t)(b * Nn + t * 32 + gw) * Dd + d;
        h[idx] += gm * acc[t];
    }
}

// ---------------------------------------------------------------------------
__global__ void head_k(const float* __restrict__ h, const float* __restrict__ w,
                       const float* __restrict__ bh, float* __restrict__ out)
{
    int m = blockIdx.x;
    int d = threadIdx.x;
    float p = h[(size_t)m * Dd + d] * w[d];
    #pragma unroll
    for (int o = 16; o > 0; o >>= 1) p += __shfl_xor_sync(0xFFFFFFFFu, p, o);
    __shared__ float s1[8];
    int lane = d & 31, wr = d >> 5;
    if (lane == 0) s1[wr] = p;
    __syncthreads();
    if (d == 0) {
        float S = 0;
        #pragma unroll
        for (int i = 0; i < 8; i++) S += s1[i];
        out[m] = S + bh[0];
    }
}

// ---------------------------------------------------------------------------
extern "C" void kernel_launch(void* const* d_in, const int* in_sizes, int n_in,
                              void* d_out, int out_size)
{
    const float* x       = (const float*)d_in[0];
    const float* w_patch = (const float*)d_in[1];
    const float* b_patch = (const float*)d_in[2];
    const float* pos     = (const float*)d_in[3];
    const float* w_edge  = (const float*)d_in[4];
    const float* b_edge  = (const float*)d_in[5];
    const float* ln_g    = (const float*)d_in[6];
    const float* ln_b    = (const float*)d_in[7];
    const float* wq      = (const float*)d_in[8];
    const float* bq      = (const float*)d_in[9];
    const float* wk      = (const float*)d_in[10];
    const float* bk      = (const float*)d_in[11];
    const float* wv      = (const float*)d_in[12];
    const float* bv      = (const float*)d_in[13];
    const float* gamma   = (const float*)d_in[14];
    const float* w1      = (const float*)d_in[15];
    const float* b1      = (const float*)d_in[16];
    const float* w2      = (const float*)d_in[17];
    const float* b2      = (const float*)d_in[18];
    const float* w_head  = (const float*)d_in[19];
    const float* b_head  = (const float*)d_in[20];
    float* out = (float*)d_out;

    float *im, *h, *xn, *lap, *qkv, *mid, *att;
    float *wpT, *weT, *wqkvT, *bqkv, *w1T, *w2T;
    cudaGetSymbolAddress((void**)&im,    g_im);
    cudaGetSymbolAddress((void**)&h,     g_h);
    cudaGetSymbolAddress((void**)&xn,    g_xn);
    cudaGetSymbolAddress((void**)&lap,   g_lap);
    cudaGetSymbolAddress((void**)&qkv,   g_qkv);
    cudaGetSymbolAddress((void**)&mid,   g_mid);
    cudaGetSymbolAddress((void**)&att,   g_att);
    cudaGetSymbolAddress((void**)&wpT,   g_wpT);
    cudaGetSymbolAddress((void**)&weT,   g_weT);
    cudaGetSymbolAddress((void**)&wqkvT, g_wqkvT);
    cudaGetSymbolAddress((void**)&bqkv,  g_bqkv);
    cudaGetSymbolAddress((void**)&w1T,   g_w1T);
    cudaGetSymbolAddress((void**)&w2T,   g_w2T);

    const int SMEM = 4 * T_STAGE * 4;   // 73728 bytes
    static bool attr_done = false;
    if (!attr_done) {
        cudaFuncSetAttribute(gemm_tc<0,1>, cudaFuncAttributeMaxDynamicSharedMemorySize, SMEM);
        cudaFuncSetAttribute(gemm_tc<1,0>, cudaFuncAttributeMaxDynamicSharedMemorySize, SMEM);
        cudaFuncSetAttribute(gemm_tc<2,0>, cudaFuncAttributeMaxDynamicSharedMemorySize, SMEM);
        cudaFuncSetAttribute(gemm_tc<3,1>, cudaFuncAttributeMaxDynamicSharedMemorySize, SMEM);
        cudaFuncSetAttribute(gemm_tc<4,0>, cudaFuncAttributeMaxDynamicSharedMemorySize, SMEM);
        attr_done = true;
    }

    const int M = Mtok;
    dim3 b256(256);

    // --- weight prep (rounded to tf32, B transposed to [N][K]) ---
    round_copy_k<<<256, b256>>>(w_patch, wpT, 65536);        // [d][k] == [n][k]
    transpose_rnd_k<<<dim3(8, 8, 1), b256>>>(w_edge, weT, 256, 256);
    pack_qkvT_k<<<2560, b256>>>(wq, wk, wv, bq, bk, bv, wqkvT, bqkv);
    transpose_rnd_k<<<dim3(32, 8, 8), b256>>>(w1, w1T, 256, 1024);
    transpose_rnd_k<<<dim3(8, 32, 8), b256>>>(w2, w2T, 1024, 256);

    // --- patch embed ---
    im2col_k<<<Mtok, b256>>>(x, im);
    gemm_tc<1,0><<<dim3(2, M / 128), b256, SMEM>>>(im, wpT, b_patch, h, pos, M, Dd, Dd);

    // --- edge tokens: h += tanh(lap(h) @ w_edge + b_edge) ---
    lap_k<<<Mtok, b256>>>(h, lap);
    gemm_tc<2,0><<<dim3(2, M / 128), b256, SMEM>>>(lap, weT, b_edge, h, nullptr, M, Dd, Dd);

    for (int l = 0; l < 8; l++) {
        ln_k<<<Mtok / 8, b256>>>(h, xn, ln_g + l * Dd, ln_b + l * Dd);
        gemm_tc<0,1><<<dim3(3, M / 128), b256, SMEM>>>(xn, wqkvT + (size_t)l * QKVW * Dd,
                                                       bqkv + l * QKVW, qkv, nullptr, M, QKVW, Dd);
        attn_score_k<<<Mtok / 8, b256>>>(qkv, att);
        attn_apply_row_k<<<Mtok / 32, b256>>>(att, qkv, xn, h, gamma, l);
        attn_apply_col_k<<<Mtok / 32, b256>>>(att, qkv, h, gamma, l);

        ln_k<<<Mtok / 8, b256>>>(h, xn, ln_g + l * Dd, ln_b + l * Dd);
        gemm_tc<3,1><<<dim3(8, M / 128), b256, SMEM>>>(xn, w1T + (size_t)l * DFf * Dd,
                                                       b1 + l * DFf, mid, nullptr, M, DFf, Dd);
        gemm_tc<4,0><<<dim3(2, M / 128), b256, SMEM>>>(mid, w2T + (size_t)l * Dd * DFf,
                                                       b2 + l * Dd, h, nullptr, M, Dd, DFf);
    }

    head_k<<<Mtok, b256>>>(h, w_head, b_head, out);
}